// round 17
// baseline (speedup 1.0000x reference)
#include <cuda_runtime.h>
#include <cuda_bf16.h>
#include <cstdint>
#include <cstddef>

// ---------------------------------------------------------------------------
// GRU (B=64, N=1024, T=512) — both GEMMs on the tensor pipe via mma.sync
// (m16n8k16 bf16, bf16x3 split: Ah*Bh + Al*Bh + Ah*Bl, fp32 accumulate).
//
// Phase 1:  XP = x @ [W1|W2] + [b1|b2]  (validated R13 kernel).
// Phase 2:  persistent kernel, 512 steps, NO global barrier:
//   fine-grained producer/consumer sync. Block b owns gate-cols b*8..b*8+7
//   (all in k-chunk b>>4). chunk_cnt[c] (release-add after update) gates
//   consumption of chunk c; g_cons (arrive after loads complete) gates
//   updates against in-flight readers of the buffer being overwritten.
//   h fp32 state lives in registers (thread owns its 2 elements).
// ---------------------------------------------------------------------------

#define Bsz 64
#define Nn  1024
#define Tt  512
#define N3  3072
#define Kd  1024
#define NB  128
#define Mrows (Bsz * Tt)   // 32768

__device__ __forceinline__ void cp16(void* s, const void* g) {
    unsigned sa = (unsigned)__cvta_generic_to_shared(s);
    asm volatile("cp.async.ca.shared.global [%0], [%1], 16;" :: "r"(sa), "l"(g));
}
__device__ __forceinline__ void cp_commit() { asm volatile("cp.async.commit_group;"); }
template <int N>
__device__ __forceinline__ void cp_wait() {
    asm volatile("cp.async.wait_group %0;" :: "n"(N));
}
__device__ __forceinline__ uint32_t smem_u32(const void* p) {
    return (uint32_t)__cvta_generic_to_shared(p);
}
__device__ __forceinline__ void ldsm4(uint32_t* r, uint32_t addr) {
    asm volatile("ldmatrix.sync.aligned.m8n8.x4.shared.b16 {%0,%1,%2,%3}, [%4];"
                 : "=r"(r[0]), "=r"(r[1]), "=r"(r[2]), "=r"(r[3]) : "r"(addr));
}
__device__ __forceinline__ void ldsm2(uint32_t* r, uint32_t addr) {
    asm volatile("ldmatrix.sync.aligned.m8n8.x2.shared.b16 {%0,%1}, [%2];"
                 : "=r"(r[0]), "=r"(r[1]) : "r"(addr));
}
__device__ __forceinline__ void mma_bf16(float* c, const uint32_t* a, const uint32_t* b) {
    asm volatile(
        "mma.sync.aligned.m16n8k16.row.col.f32.bf16.bf16.f32 "
        "{%0,%1,%2,%3}, {%4,%5,%6,%7}, {%8,%9}, {%0,%1,%2,%3};"
        : "+f"(c[0]), "+f"(c[1]), "+f"(c[2]), "+f"(c[3])
        : "r"(a[0]), "r"(a[1]), "r"(a[2]), "r"(a[3]), "r"(b[0]), "r"(b[1]));
}

// ------------------------- device scratch ----------------------------------
__device__ float g_XP[(size_t)Mrows * N3];               // 402 MB
__device__ __nv_bfloat16 g_Ahi[(size_t)Mrows * Kd];      // [m][k]
__device__ __nv_bfloat16 g_Alo[(size_t)Mrows * Kd];
__device__ __nv_bfloat16 g_Bhi[(size_t)N3 * Kd];         // [n][k] = W^T
__device__ __nv_bfloat16 g_Blo[(size_t)N3 * Kd];
__device__ __nv_bfloat16 g_Hhi[2][Bsz * Nn];             // bf16 h hi, [m][k]
__device__ __nv_bfloat16 g_Hlo[2][Bsz * Nn];             // bf16 h lo, [m][k]

__device__ unsigned g_chunk_cnt[8];   // per-k-chunk producer counters (cumulative)
__device__ unsigned g_cons;           // per-step load-completion counter

__global__ void init_state() {
    int i = blockIdx.x * 256 + threadIdx.x;
    if (i < Nn * Bsz) {
        g_Hhi[0][i] = __float2bfloat16(0.f);
        g_Hlo[0][i] = __float2bfloat16(0.f);
    }
    if (i < 8) g_chunk_cnt[i] = 0;
    if (i == 0) g_cons = 0;
}

// lane0-per-warp spin on a monotone counter, warp-converged exit
__device__ __forceinline__ void wait_ge(unsigned* p, unsigned target) {
    if ((threadIdx.x & 31) == 0) {
        while (*(volatile unsigned*)p < target) __nanosleep(32);
    }
    __syncwarp();
}

// ------------------------- converts ----------------------------------------
__global__ void conv_a(const float* __restrict__ fx) {
    __shared__ float tile[32][33];
    int k0 = blockIdx.x * 32, t0 = blockIdx.y * 32, b = blockIdx.z;
    int tx = threadIdx.x & 31, ty = threadIdx.x >> 5;
#pragma unroll
    for (int i = 0; i < 4; i++)
        tile[ty + 8 * i][tx] = fx[((size_t)b * Kd + k0 + ty + 8 * i) * Tt + t0 + tx];
    __syncthreads();
#pragma unroll
    for (int i = 0; i < 4; i++) {
        float v = tile[tx][ty + 8 * i];
        __nv_bfloat16 hi = __float2bfloat16(v);
        __nv_bfloat16 lo = __float2bfloat16(v - __bfloat162float(hi));
        size_t idx = ((size_t)b * Tt + t0 + ty + 8 * i) * Kd + k0 + tx;
        g_Ahi[idx] = hi;
        g_Alo[idx] = lo;
    }
}

__global__ void conv_w(const float* __restrict__ W1, const float* __restrict__ W2) {
    __shared__ float tile[32][33];
    int k0 = blockIdx.x * 32, n0 = blockIdx.y * 32;
    int tx = threadIdx.x & 31, ty = threadIdx.x >> 5;
    const float* src; int stride, nb;
    if (n0 < 2048) { src = W1; stride = 2048; nb = n0; }
    else           { src = W2; stride = 1024; nb = n0 - 2048; }
#pragma unroll
    for (int i = 0; i < 4; i++)
        tile[ty + 8 * i][tx] = src[(size_t)(k0 + ty + 8 * i) * stride + nb + tx];
    __syncthreads();
#pragma unroll
    for (int i = 0; i < 4; i++) {
        float v = tile[tx][ty + 8 * i];
        __nv_bfloat16 hi = __float2bfloat16(v);
        __nv_bfloat16 lo = __float2bfloat16(v - __bfloat162float(hi));
        size_t idx = (size_t)(n0 + ty + 8 * i) * Kd + k0 + tx;
        g_Bhi[idx] = hi;
        g_Blo[idx] = lo;
    }
}

// ------------------------- phase 1: mma.sync xproj (R13, unchanged) ---------
#define XR       40
#define XARR     (128 * XR)
#define XBUF     (4 * XARR)
#define XSMEM    (2 * XBUF * 2)

__global__ __launch_bounds__(256, 2) void xproj_mma(
        const float* __restrict__ b1, const float* __restrict__ b2) {
    extern __shared__ __nv_bfloat16 xsm[];

    const int tid = threadIdx.x;
    const int wid = tid >> 5, lane = tid & 31;
    const int n0 = blockIdx.x * 128;
    const int m0 = blockIdx.y * 128;
    const int wm = (wid & 3) * 32;
    const int wn = (wid >> 2) * 64;

    auto issue = [&](int c, int buf) {
        __nv_bfloat16* base = xsm + buf * XBUF;
#pragma unroll
        for (int j = 0; j < 8; j++) {
            int l = tid + j * 256;
            int arr = l >> 9;
            int r   = (l >> 2) & 127;
            int seg = l & 3;
            const __nv_bfloat16* gsrc;
            if (arr == 0)      gsrc = g_Ahi + (size_t)(m0 + r) * Kd + c * 32 + seg * 8;
            else if (arr == 1) gsrc = g_Alo + (size_t)(m0 + r) * Kd + c * 32 + seg * 8;
            else if (arr == 2) gsrc = g_Bhi + (size_t)(n0 + r) * Kd + c * 32 + seg * 8;
            else               gsrc = g_Blo + (size_t)(n0 + r) * Kd + c * 32 + seg * 8;
            cp16(base + arr * XARR + r * XR + seg * 8, gsrc);
        }
        cp_commit();
    };

    float acc[2][8][4];
#pragma unroll
    for (int mt = 0; mt < 2; mt++)
#pragma unroll
        for (int nt = 0; nt < 8; nt++)
#pragma unroll
            for (int i = 0; i < 4; i++) acc[mt][nt][i] = 0.f;

    issue(0, 0);
    int buf = 0;
    for (int c = 0; c < Kd / 32; c++) {
        const bool more = (c + 1 < Kd / 32);
        if (more) { issue(c + 1, buf ^ 1); cp_wait<1>(); }
        else      { cp_wait<0>(); }
        __syncthreads();

        __nv_bfloat16* bp = xsm + buf * XBUF;
        const int arow  = lane & 15;
        const int akoff = (lane >> 4) << 3;
        const int brow  = (lane & 7) + ((lane >> 4) << 3);
        const int bkoff = ((lane >> 3) & 1) << 3;

#pragma unroll
        for (int kk = 0; kk < 32; kk += 16) {
            uint32_t ah[2][4], al[2][4], bb[4][4];
#pragma unroll
            for (int mt = 0; mt < 2; mt++) {
                uint32_t ad = smem_u32(bp + (wm + mt * 16 + arow) * XR + kk + akoff);
                ldsm4(ah[mt], ad);
                ldsm4(al[mt], ad + XARR * 2);
            }
#pragma unroll
            for (int nt = 0; nt < 4; nt++) {
                uint32_t bd = smem_u32(bp + 2 * XARR + (wn + nt * 16 + brow) * XR + kk + bkoff);
                ldsm4(bb[nt], bd);
            }
#pragma unroll
            for (int mt = 0; mt < 2; mt++)
#pragma unroll
                for (int nt = 0; nt < 4; nt++) {
                    mma_bf16(acc[mt][nt * 2],     ah[mt], &bb[nt][0]);
                    mma_bf16(acc[mt][nt * 2 + 1], ah[mt], &bb[nt][2]);
                    mma_bf16(acc[mt][nt * 2],     al[mt], &bb[nt][0]);
                    mma_bf16(acc[mt][nt * 2 + 1], al[mt], &bb[nt][2]);
                }
#pragma unroll
            for (int nt = 0; nt < 4; nt++) {
                uint32_t bd = smem_u32(bp + 3 * XARR + (wn + nt * 16 + brow) * XR + kk + bkoff);
                ldsm4(bb[nt], bd);
            }
#pragma unroll
            for (int mt = 0; mt < 2; mt++)
#pragma unroll
                for (int nt = 0; nt < 4; nt++) {
                    mma_bf16(acc[mt][nt * 2],     ah[mt], &bb[nt][0]);
                    mma_bf16(acc[mt][nt * 2 + 1], ah[mt], &bb[nt][2]);
                }
        }
        __syncthreads();
        buf ^= 1;
    }

    const int g = lane >> 2, tig = lane & 3;
#pragma unroll
    for (int mt = 0; mt < 2; mt++) {
#pragma unroll
        for (int nt = 0; nt < 8; nt++) {
            int n = n0 + wn + nt * 8 + tig * 2;
            float bv0 = (n < 2048) ? b1[n] : b2[n - 2048];
            float bv1 = (n + 1 < 2048) ? b1[n + 1] : b2[n + 1 - 2048];
            int m = m0 + wm + mt * 16 + g;
            float2 v0 = {acc[mt][nt][0] + bv0, acc[mt][nt][1] + bv1};
            float2 v1 = {acc[mt][nt][2] + bv0, acc[mt][nt][3] + bv1};
            *(float2*)&g_XP[(size_t)m * N3 + n] = v0;
            *(float2*)&g_XP[(size_t)(m + 8) * N3 + n] = v1;
        }
    }
}

// ------------------------- phase 2: tensor-core recurrence ------------------
#define BS_STR  1032
#define HT_STR  136
#define R_BS    (24 * BS_STR)
#define R_HT    (64 * HT_STR)
#define R_HBUF  (2 * R_HT)
#define R_PS    (2 * 64 * 26)
#define RSMEM   ((2 * R_BS + 2 * R_HBUF) * 2 + R_PS * 4 + 128)

__global__ __launch_bounds__(256, 1) void recurrence(
        const float* __restrict__ b1, const float* __restrict__ b2,
        float* __restrict__ out) {
    extern __shared__ __nv_bfloat16 rsm[];
    __nv_bfloat16* Bs_hi = rsm;                       // [24][1032]
    __nv_bfloat16* Bs_lo = Bs_hi + R_BS;
    __nv_bfloat16* hring = Bs_lo + R_BS;              // [2][hi|lo][64][136]
    float* p_s    = (float*)(hring + 2 * R_HBUF);     // [2][64][26]
    float* bias_s = p_s + R_PS;                       // [24]

    const int tid = threadIdx.x;
    const int blk = blockIdx.x;
    const int wid = tid >> 5, lane = tid & 31;
    const int gc0 = blk * 8;
    const int myc = blk >> 4;                         // this block's h chunk
    const int wm  = (wid & 3) * 16;
    const int khw = wid >> 2;                         // in-chunk k-split 0..1

    // ---- resident B slice: 24 rows (gc0+i, 1024+gc0+i, 2048+gc0+i) ---------
#pragma unroll
    for (int j = 0; j < 24; j++) {
        int l = tid + j * 256;
        int arr = l >= 3072;
        int l2 = l - arr * 3072;
        int row = l2 >> 7, seg = l2 & 127;
        int p = row >> 3, ii = row & 7;
        int n = p * 1024 + gc0 + ii;
        const __nv_bfloat16* gsrc = (arr ? g_Blo : g_Bhi) + (size_t)n * Kd + seg * 8;
        __nv_bfloat16* dst = (arr ? Bs_lo : Bs_hi) + row * BS_STR + seg * 8;
        cp16(dst, gsrc);
    }
    cp_commit();
    if (tid < 24) {
        int p = tid >> 3, ii = tid & 7, n = gc0 + ii;
        bias_s[tid] = (p == 0) ? b1[n] : (p == 1) ? b1[1024 + n] : b2[n];
    }
    cp_wait<0>();
    __syncthreads();

    const int arow  = lane & 15;
    const int akoff = (lane >> 4) << 3;
    const int brow  = (lane & 7) + ((lane >> 4) << 3);
    const int bkoff = ((lane >> 3) & 1) << 3;
    const int brow2 = lane & 7;
    const int g = lane >> 2, tig = lane & 3;

    const int um = tid & 63;                          // update row (batch m)
    const int ui = tid >> 6;                          // update gate-col 0..3

    float hreg[2] = {0.f, 0.f};                       // own fp32 h state

    for (int t = 0; t < Tt; t++) {
        const __nv_bfloat16* hhi_c = g_Hhi[t & 1];
        const __nv_bfloat16* hlo_c = g_Hlo[t & 1];
        const unsigned ctarget = 16u * (unsigned)t;

        // issue one 128-k h chunk (chunk index ck8) into ring buffer rb
        auto hissue = [&](int ck8, int rb) {
            __nv_bfloat16* d_hi = hring + rb * R_HBUF;
            __nv_bfloat16* d_lo = d_hi + R_HT;
#pragma unroll
            for (int j = 0; j < 4; j++) {
                int l = tid + j * 256;
                int row = l >> 4, seg = l & 15;
                size_t src = (size_t)row * Kd + ck8 * 128 + seg * 8;
                cp16(d_hi + row * HT_STR + seg * 8, hhi_c + src);
                cp16(d_lo + row * HT_STR + seg * 8, hlo_c + src);
            }
            cp_commit();
        };

        // prefetch gating inputs (XP only; h state is in registers)
        float xq[2][3];
#pragma unroll
        for (int e = 0; e < 2; e++) {
            int m = um, i = ui + e * 4, n = gc0 + i;
            const float* xp = g_XP + ((size_t)(m * Tt + t)) * N3 + n;
            xq[e][0] = xp[0]; xq[e][1] = xp[1024]; xq[e][2] = xp[2048];
        }

        float acc[3][4];
#pragma unroll
        for (int nt = 0; nt < 3; nt++)
#pragma unroll
            for (int i = 0; i < 4; i++) acc[nt][i] = 0.f;

        // chunk iteration order starts at own chunk (self-arrives first)
        {
            int c0 = myc;
            wait_ge(&g_chunk_cnt[c0], ctarget);
            __threadfence();
            hissue(c0, 0);
        }
        for (int i = 0; i < 8; i++) {
            const int ci = (myc + i) & 7;
            if (i < 7) {
                int cn = (myc + i + 1) & 7;
                wait_ge(&g_chunk_cnt[cn], ctarget);
                __threadfence();
                hissue(cn, (i + 1) & 1);
                cp_wait<1>();
            } else {
                cp_wait<0>();
            }
            __syncthreads();
            if (i == 7 && tid == 0) atomicAdd(&g_cons, 1u);  // loads of step t done

            __nv_bfloat16* hA_hi = hring + (i & 1) * R_HBUF;
            __nv_bfloat16* hA_lo = hA_hi + R_HT;
            const int cks = khw * 64;

#pragma unroll
            for (int q = 0; q < 4; q++) {
                const int kk = cks + q * 16;
                uint32_t ah[4], al[4], bh[4], bh2[2], bl[4], bl2[2];
                uint32_t ad = smem_u32(hA_hi + (wm + arow) * HT_STR + kk + akoff);
                ldsm4(ah, ad);
                ldsm4(al, smem_u32(hA_lo + (wm + arow) * HT_STR + kk + akoff));
                const int bk = ci * 128 + kk;
                ldsm4(bh,  smem_u32(Bs_hi + brow * BS_STR + bk + bkoff));
                ldsm2(bh2, smem_u32(Bs_hi + (16 + brow2) * BS_STR + bk + bkoff));
                ldsm4(bl,  smem_u32(Bs_lo + brow * BS_STR + bk + bkoff));
                ldsm2(bl2, smem_u32(Bs_lo + (16 + brow2) * BS_STR + bk + bkoff));
                mma_bf16(acc[0], ah, &bh[0]);
                mma_bf16(acc[1], ah, &bh[2]);
                mma_bf16(acc[2], ah, bh2);
                mma_bf16(acc[0], al, &bh[0]);
                mma_bf16(acc[1], al, &bh[2]);
                mma_bf16(acc[2], al, bh2);
                mma_bf16(acc[0], ah, &bl[0]);
                mma_bf16(acc[1], ah, &bl[2]);
                mma_bf16(acc[2], ah, bl2);
            }
            __syncthreads();
        }

        // ---- partials to smem: p_s[khw][row][col] ---------------------------
#pragma unroll
        for (int nt = 0; nt < 3; nt++) {
            int col = nt * 8 + tig * 2;
            float* p0 = p_s + (khw * 64 + wm + g) * 26 + col;
            float* p1 = p_s + (khw * 64 + wm + g + 8) * 26 + col;
            *(float2*)p0 = make_float2(acc[nt][0], acc[nt][1]);
            *(float2*)p1 = make_float2(acc[nt][2], acc[nt][3]);
        }
        __syncthreads();

        // ---- back-pressure: all blocks must have finished step t-1 loads ----
        wait_ge(&g_cons, 128u * (unsigned)t);
        __syncthreads();

        // ---- fused reduce + gates + h update (block-local) ------------------
        __nv_bfloat16* hhi_n = g_Hhi[(t + 1) & 1];
        __nv_bfloat16* hlo_n = g_Hlo[(t + 1) & 1];
#pragma unroll
        for (int e = 0; e < 2; e++) {
            int m = um, i = ui + e * 4, n = gc0 + i;
            float s1 = p_s[m * 26 + i]        + p_s[(64 + m) * 26 + i];
            float s2 = p_s[m * 26 + 8 + i]    + p_s[(64 + m) * 26 + 8 + i];
            float sh = p_s[m * 26 + 16 + i]   + p_s[(64 + m) * 26 + 16 + i];
            // reference adds biases in BOTH x-proj and h-proj — replicate
            float z = 1.f / (1.f + expf(-(xq[e][0] + s1 + bias_s[i])));
            float r = 1.f / (1.f + expf(-(xq[e][1] + s2 + bias_s[8 + i])));
            float hrec = sh + bias_s[16 + i];
            float hn = z * hreg[e] + (1.f - z) * tanhf(xq[e][2] + r * hrec);
            hreg[e] = hn;
            __nv_bfloat16 hhi = __float2bfloat16(hn);
            __nv_bfloat16 hlo = __float2bfloat16(hn - __bfloat162float(hhi));
            hhi_n[m * Nn + n] = hhi;
            hlo_n[m * Nn + n] = hlo;
            if (t == Tt - 1) out[m * Nn + n] = hn;
        }

        // ---- publish: own chunk's h slice is ready for step t+1 -------------
        __threadfence();
        __syncthreads();
        if (tid == 0) atomicAdd(&g_chunk_cnt[myc], 1u);
    }
}

// ---------------------------------------------------------------------------
extern "C" void kernel_launch(void* const* d_in, const int* in_sizes, int n_in,
                              void* d_out, int out_size) {
    const float *fx = nullptr, *W1 = nullptr, *b1 = nullptr, *W2 = nullptr, *b2 = nullptr;
    for (int i = 0; i < n_in; i++) {
        switch (in_sizes[i]) {
            case Bsz * Nn * Tt:  fx = (const float*)d_in[i]; break;
            case Nn * 2 * Nn:    W1 = (const float*)d_in[i]; break;
            case 2 * Nn:         b1 = (const float*)d_in[i]; break;
            case Nn * Nn:        W2 = (const float*)d_in[i]; break;
            case Nn:             b2 = (const float*)d_in[i]; break;
            default: break;
        }
    }
    float* out = (float*)d_out;

    cudaFuncSetAttribute(xproj_mma,  cudaFuncAttributeMaxDynamicSharedMemorySize, XSMEM);
    cudaFuncSetAttribute(recurrence, cudaFuncAttributeMaxDynamicSharedMemorySize, RSMEM);

    init_state<<<(Nn * Bsz + 255) / 256, 256>>>();

    conv_a<<<dim3(Kd / 32, Tt / 32, Bsz), 256>>>(fx);
    conv_w<<<dim3(Kd / 32, N3 / 32), 256>>>(W1, W2);

    xproj_mma<<<dim3(N3 / 128, Mrows / 128), 256, XSMEM>>>(b1, b2);

    recurrence<<<NB, 256, RSMEM>>>(b1, b2, out);
}